// round 8
// baseline (speedup 1.0000x reference)
#include <cuda_runtime.h>
#include <cstdint>

#define S_LEN 2048
#define BATCH 32
#define HID   256
#define NCOL  1024   // 4*H
#define HROW  320    // 256 + 4-float pad per 16 floats (conflict-free LDS phases)

// 256 MB scratch for Zx = x @ Wx + b, layout [s][b][j]
__device__ float g_zx[(size_t)S_LEN * BATCH * NCOL];

// ----------------------------- helpers -----------------------------
__device__ __forceinline__ void fma2(unsigned long long &d, unsigned long long a, unsigned long long b) {
    asm("fma.rn.f32x2 %0, %1, %2, %0;" : "+l"(d) : "l"(a), "l"(b));
}
__device__ __forceinline__ unsigned long long pack2(float lo, float hi) {
    unsigned long long r; asm("mov.b64 %0, {%1, %2};" : "=l"(r) : "f"(lo), "f"(hi)); return r;
}
__device__ __forceinline__ float lo32(unsigned long long v){ return __uint_as_float((unsigned)(v & 0xffffffffull)); }
__device__ __forceinline__ float hi32(unsigned long long v){ return __uint_as_float((unsigned)(v >> 32)); }
__device__ __forceinline__ unsigned smem_u32(const void* p){ return (unsigned)__cvta_generic_to_shared(p); }
__device__ __forceinline__ unsigned mapa_rank(unsigned a, unsigned rk){
    unsigned r; asm("mapa.shared::cluster.u32 %0, %1, %2;" : "=r"(r) : "r"(a), "r"(rk)); return r;
}
__device__ __forceinline__ void cluster_sync_(){
    asm volatile("barrier.cluster.arrive.aligned;" ::: "memory");
    asm volatile("barrier.cluster.wait.aligned;" ::: "memory");
}
__device__ __forceinline__ float tanha(float x){
    float y; asm("tanh.approx.f32 %0, %1;" : "=f"(y) : "f"(x)); return y;
}
__device__ __forceinline__ float sig(float x){ return fmaf(0.5f, tanha(0.5f * x), 0.5f); }

__device__ __forceinline__ void mbar_init(unsigned bar, unsigned cnt){
    asm volatile("mbarrier.init.shared.b64 [%0], %1;" :: "r"(bar), "r"(cnt) : "memory");
}
__device__ __forceinline__ void mbar_arm(unsigned bar, unsigned tx){
    asm volatile("mbarrier.arrive.expect_tx.shared.b64 _, [%0], %1;" :: "r"(bar), "r"(tx) : "memory");
}
__device__ __forceinline__ void mbar_wait(unsigned bar, unsigned parity){
    asm volatile(
        "{\n\t.reg .pred P;\n\t"
        "WL_%=:\n\t"
        "mbarrier.try_wait.parity.acquire.cluster.shared::cta.b64 P, [%0], %1, 0x989680;\n\t"
        "@!P bra WL_%=;\n\t}"
        :: "r"(bar), "r"(parity) : "memory");
}
// remote 8-byte store + remote mbarrier tx-completion in one instruction
__device__ __forceinline__ void st_async_b64(unsigned raddr, unsigned rbar, unsigned long long v){
    asm volatile("st.async.shared::cluster.mbarrier::complete_tx::bytes.b64 [%0], %1, [%2];"
                 :: "r"(raddr), "l"(v), "r"(rbar) : "memory");
}

// ----------------------------- phase 1: Zx = x @ Wx + b (+ tail zeroing) -----------------------------
// f32x2-packed microtile: 4 row-pairs x 8 cols per thread. a-pairs load directly
// as 64-bit from As (adjacent rows); b broadcast-packed once per col per kk.
__global__ void __launch_bounds__(256, 2)
gemm_x_kernel(const float* __restrict__ x, const float* __restrict__ W, const float* __restrict__ bias,
              float* __restrict__ out, long long tail_start, long long tail_n)
{
    __shared__ float As[32][128];
    __shared__ float Bs[32][128];

    const int tid = threadIdx.x;

    if (blockIdx.x == 0 && blockIdx.y < 64) {
        long long i = (long long)blockIdx.y * 256 + tid;
        if (i < tail_n) out[tail_start + i] = 0.0f;
    }

    const int colTile = blockIdx.x * 128;
    const int rowTile = blockIdx.y * 128;
    const int tx = tid & 15, ty = tid >> 4;

    unsigned long long accp[4][8];   // [row-pair][col] = (acc[2i][j], acc[2i+1][j])
    #pragma unroll
    for (int i = 0; i < 4; i++)
        #pragma unroll
        for (int j = 0; j < 8; j++) accp[i][j] = 0ull;

    const int arow = tid >> 3;
    const int akk  = (tid & 7) * 4;
    const int bkk  = tid >> 3;
    const int bj   = (tid & 7) * 16;

    for (int k0 = 0; k0 < 256; k0 += 32) {
        #pragma unroll
        for (int wv = 0; wv < 4; wv++) {
            int row = arow + wv * 32;
            int rr  = rowTile + row;
            int bb  = rr & 31;
            int ss  = rr >> 5;
            float4 v = *(const float4*)&x[((size_t)bb * S_LEN + ss) * 256 + k0 + akk];
            As[akk + 0][row] = v.x; As[akk + 1][row] = v.y;
            As[akk + 2][row] = v.z; As[akk + 3][row] = v.w;
        }
        #pragma unroll
        for (int wv = 0; wv < 4; wv++) {
            float4 v = *(const float4*)&W[(size_t)(k0 + bkk) * NCOL + colTile + bj + wv * 4];
            *(float4*)&Bs[bkk][bj + wv * 4] = v;
        }
        __syncthreads();

        #pragma unroll
        for (int kk = 0; kk < 32; kk++) {
            ulonglong2 A0 = *(const ulonglong2*)&As[kk][ty * 8];      // pairs (r0,r1),(r2,r3)
            ulonglong2 A1 = *(const ulonglong2*)&As[kk][ty * 8 + 4];  // pairs (r4,r5),(r6,r7)
            float4 b0 = *(const float4*)&Bs[kk][tx * 8];
            float4 b1 = *(const float4*)&Bs[kk][tx * 8 + 4];
            unsigned long long ap[4] = {A0.x, A0.y, A1.x, A1.y};
            float bsv[8] = {b0.x, b0.y, b0.z, b0.w, b1.x, b1.y, b1.z, b1.w};
            #pragma unroll
            for (int j = 0; j < 8; j++) {
                unsigned long long bb = pack2(bsv[j], bsv[j]);
                #pragma unroll
                for (int i = 0; i < 4; i++) fma2(accp[i][j], ap[i], bb);
            }
        }
        __syncthreads();
    }

    float bv[8];
    #pragma unroll
    for (int j = 0; j < 8; j++) bv[j] = bias[colTile + tx * 8 + j];

    #pragma unroll
    for (int i = 0; i < 4; i++) {
        size_t rr0 = (size_t)rowTile + ty * 8 + 2 * i;
        float4 e0, e1, o0, o1;
        e0.x = lo32(accp[i][0]) + bv[0]; e0.y = lo32(accp[i][1]) + bv[1];
        e0.z = lo32(accp[i][2]) + bv[2]; e0.w = lo32(accp[i][3]) + bv[3];
        e1.x = lo32(accp[i][4]) + bv[4]; e1.y = lo32(accp[i][5]) + bv[5];
        e1.z = lo32(accp[i][6]) + bv[6]; e1.w = lo32(accp[i][7]) + bv[7];
        o0.x = hi32(accp[i][0]) + bv[0]; o0.y = hi32(accp[i][1]) + bv[1];
        o0.z = hi32(accp[i][2]) + bv[2]; o0.w = hi32(accp[i][3]) + bv[3];
        o1.x = hi32(accp[i][4]) + bv[4]; o1.y = hi32(accp[i][5]) + bv[5];
        o1.z = hi32(accp[i][6]) + bv[6]; o1.w = hi32(accp[i][7]) + bv[7];
        *(float4*)&g_zx[rr0 * NCOL + colTile + tx * 8]           = e0;
        *(float4*)&g_zx[rr0 * NCOL + colTile + tx * 8 + 4]       = e1;
        *(float4*)&g_zx[(rr0 + 1) * NCOL + colTile + tx * 8]     = o0;
        *(float4*)&g_zx[(rr0 + 1) * NCOL + colTile + tx * 8 + 4] = o1;
    }
}

// ----------------------------- phase 2: the recurrence -----------------------------
// 16 clusters x 8 CTAs, cluster p owns chains 2p, 2p+1. CTA rank r owns hidden
// units [r*32, r*32+32). Thread t = m*16 + ks. After the butterfly reduction all
// 16 lanes of a half-warp hold all 8 sums; lanes 0/1/16/17 each finish ONE
// (chain, unit) tail. 4 shfl.idx gather the unit-pair; lanes 0-7 send chain-0
// pairs, lanes 16-23 chain-1 pairs — one 8-byte st.async per lane to its rank
// (256 parallel messages/CTA/step instead of 512 serialized b32).
__global__ void __cluster_dims__(8, 1, 1) __launch_bounds__(512, 1)
lstm_chain_kernel(const float* __restrict__ W, const float* __restrict__ h0,
                  const float* __restrict__ c0, float* __restrict__ out)
{
    __shared__ __align__(16) float h_buf[2][2][HROW];   // [parity][chain][padded k]
    __shared__ __align__(8) unsigned long long mbar[2];

    const int tid  = threadIdx.x;
    const int p    = blockIdx.x >> 3;
    const int r    = blockIdx.x & 7;
    const int lane = tid & 31;

    const int m  = tid >> 4;     // 0..31 hidden unit (local)
    const int ks = tid & 15;     // k-slice

    // ---- weights: w2[g*8+q] covers k = ks*16 + 2q, 2q+1, col = g*256 + r*32 + m
    unsigned long long w2[32];
    {
        const float* Wb = W + (size_t)(256 + ks * 16) * NCOL + r * 32 + m;
        #pragma unroll
        for (int g = 0; g < 4; g++)
            #pragma unroll
            for (int q = 0; q < 8; q++)
                w2[g * 8 + q] = pack2(Wb[(size_t)(2 * q) * NCOL + g * 256],
                                      Wb[(size_t)(2 * q + 1) * NCOL + g * 256]);
    }

    // ---- barrier init + pre-arm
    const unsigned hb_base = smem_u32(&h_buf[0][0][0]);
    const unsigned mb_base = smem_u32(&mbar[0]);
    const int dMB = (int)(mb_base - hb_base);
    if (tid == 511) {
        mbar_init(mb_base, 1);
        mbar_init(mb_base + 8, 1);
        mbar_arm(mb_base, 2048);      // receives step-1 stores, waited step 2
        mbar_arm(mb_base + 8, 2048);  // receives step-0 stores, waited step 1
    }

    // ---- init h_buf[0] (padded layout: +4 floats per 16)
    {
        int ch = tid >> 8, k = tid & 255;
        h_buf[0][ch][k + ((k >> 4) << 2)] = h0[(size_t)(2 * p + ch) * HID + k];
    }

    // ---- computing lanes: ks<2 -> this lane owns (chain=ks, unit m)
    const int myc = ks;                      // chain for ks<2
    float cst = 0.0f;
    if (ks < 2) cst = c0[(size_t)(2 * p + myc) * HID + r * 32 + m];

    // ---- remote store bases (rank-mapped h_buf base; peer mbar = +dMB)
    unsigned hmap[8];
    #pragma unroll
    for (int rk = 0; rk < 8; rk++) hmap[rk] = mapa_rank(hb_base, rk);

    // even unit of this warp (units 2w, 2w+1 live in one warp)
    const int m0  = 2 * (tid >> 5);
    const int kg0 = r * 32 + m0;
    const int po0 = kg0 + ((kg0 >> 4) << 2);   // padded offset, 8B-aligned (kg0 even)

    const float* zx_base = g_zx + (size_t)(2 * p + (ks < 2 ? myc : 0)) * NCOL + r * 32 + m;
    float* out_base = out + ((size_t)(2 * p + (ks < 2 ? myc : 0)) * S_LEN) * HID + r * 32 + m;

    // sender role: lanes 0-7 -> chain 0 to rank=lane; lanes 16-23 -> chain 1 to rank=lane-16
    const bool sender = (lane < 8) || (lane >= 16 && lane < 24);
    const int  s_ch   = (lane < 8) ? 0 : 1;
    const int  s_rk   = lane & 7;

    __syncthreads();
    cluster_sync_();   // barriers init'd + h_buf[0] ready cluster-wide

    int ph0 = 0, ph1 = 0;

    for (int s = 0; s < S_LEN; s++) {
        const int par = s & 1;

        // zx loads first — independent of peers, latency hides under the wait+FMA
        float zxv[4];
        if (ks < 2) {
            const float* zp = zx_base + (size_t)s * (BATCH * NCOL);
            #pragma unroll
            for (int g = 0; g < 4; g++) zxv[g] = __ldg(zp + g * 256);
        }

        if (s > 0) {
            unsigned bar = mb_base + (unsigned)par * 8;
            int ph = par ? ph1 : ph0;
            mbar_wait(bar, (unsigned)ph);
            if (par) ph1 ^= 1; else ph0 ^= 1;
            if (tid == 511) mbar_arm(bar, 2048);   // re-arm for step s+2
        }

        // ---- Wh . h over this thread's 16-k slice, 4 gates, 2 chains
        unsigned long long accA[4] = {0,0,0,0}, accB[4] = {0,0,0,0};
        {
            const ulonglong2* hb = (const ulonglong2*)&h_buf[par][0][ks * 20];
            ulonglong2 q0 = hb[0], q1 = hb[1], q2 = hb[2], q3 = hb[3];
            unsigned long long h8[8] = {q0.x, q0.y, q1.x, q1.y, q2.x, q2.y, q3.x, q3.y};
            #pragma unroll
            for (int g = 0; g < 4; g++)
                #pragma unroll
                for (int q = 0; q < 8; q++) fma2(accA[g], w2[g * 8 + q], h8[q]);
        }
        {
            const ulonglong2* hb = (const ulonglong2*)&h_buf[par][1][ks * 20];
            ulonglong2 q0 = hb[0], q1 = hb[1], q2 = hb[2], q3 = hb[3];
            unsigned long long h8[8] = {q0.x, q0.y, q1.x, q1.y, q2.x, q2.y, q3.x, q3.y};
            #pragma unroll
            for (int g = 0; g < 4; g++)
                #pragma unroll
                for (int q = 0; q < 8; q++) fma2(accB[g], w2[g * 8 + q], h8[q]);
        }

        float sv[8];
        #pragma unroll
        for (int g = 0; g < 4; g++) {
            sv[g]     = lo32(accA[g]) + hi32(accA[g]);
            sv[4 + g] = lo32(accB[g]) + hi32(accB[g]);
        }
        // butterfly over the 16 k-slices (ks = lane bits 0..3): every lane gets the sums
        #pragma unroll
        for (int v = 0; v < 8; v++) {
            sv[v] += __shfl_xor_sync(0xffffffffu, sv[v], 1);
            sv[v] += __shfl_xor_sync(0xffffffffu, sv[v], 2);
            sv[v] += __shfl_xor_sync(0xffffffffu, sv[v], 4);
            sv[v] += __shfl_xor_sync(0xffffffffu, sv[v], 8);
        }

        // ---- per-lane tail: lanes 0/1/16/17 each finish one (chain, unit)
        float hn = 0.0f;
        if (ks < 2) {
            const int b0 = myc * 4;
            float zi = tanha(sv[b0 + 0] + zxv[0]);
            float zf = tanha(sv[b0 + 1] + zxv[1]);
            float zg = tanha(sv[b0 + 2] + zxv[2]);
            float zo = tanha(sv[b0 + 3] + zxv[3]);
            cst = sig(zf) * cst + sig(zi) * tanha(zg);
            hn  = tanha(cst) * sig(zo);
        }

        // gather unit-pair values to all lanes (4 shfl.idx)
        float he0 = __shfl_sync(0xffffffffu, hn, 0);    // chain0, even unit
        float he1 = __shfl_sync(0xffffffffu, hn, 1);    // chain1, even unit
        float ho0 = __shfl_sync(0xffffffffu, hn, 16);   // chain0, odd unit
        float ho1 = __shfl_sync(0xffffffffu, hn, 17);   // chain1, odd unit

        if (sender && (s + 1 < S_LEN)) {
            const int parN = par ^ 1;
            unsigned long long pv = (s_ch == 0) ? pack2(he0, ho0) : pack2(he1, ho1);
            unsigned off = (unsigned)(((parN * 2 + s_ch) * HROW + po0) * 4);
            unsigned mbo = (unsigned)(dMB + parN * 8);
            st_async_b64(hmap[s_rk] + off, hmap[s_rk] + mbo, pv);
        }

        if (ks < 2)
            out_base[(size_t)s * HID] = hn;
    }

    // no CTA may exit while peers could still have remote stores in flight
    cluster_sync_();
}

// ----------------------------- launcher -----------------------------
extern "C" void kernel_launch(void* const* d_in, const int* in_sizes, int n_in,
                              void* d_out, int out_size) {
    const float* x    = (const float*)d_in[0];   // (32, 2048, 256)
    const float* h0   = (const float*)d_in[1];   // (1, 32, 256)
    const float* c0   = (const float*)d_in[2];   // (1, 32, 256)
    const float* W    = (const float*)d_in[3];   // (512, 1024)
    const float* bias = (const float*)d_in[4];   // (1024,)
    float* out = (float*)d_out;

    const long long main_elems = (long long)BATCH * S_LEN * HID;
    const long long tail = (long long)out_size - main_elems;

    gemm_x_kernel<<<dim3(8, 512, 1), 256>>>(x, W, bias, out, main_elems, tail > 0 ? tail : 0);
    lstm_chain_kernel<<<128, 512>>>(W, h0, c0, out);
}

// round 9
// speedup vs baseline: 1.2669x; 1.2669x over previous
#include <cuda_runtime.h>
#include <cstdint>

#define S_LEN 2048
#define BATCH 32
#define HID   256
#define NCOL  1024   // 4*H
#define HROW  320    // 256 + 4-float pad per 16 floats (conflict-free LDS phases)

// 256 MB scratch for Zx = x @ Wx + b.
// Layout: [s][b][jp] with jp = r*128 + g*32 + m  (r = cluster rank owning the
// column, g = gate, m = unit-within-rank). Each CTA's per-step slice per chain
// is one contiguous 512B block -> cp.async.bulk friendly.
__device__ float g_zx[(size_t)S_LEN * BATCH * NCOL];

// ----------------------------- helpers -----------------------------
__device__ __forceinline__ void fma2(unsigned long long &d, unsigned long long a, unsigned long long b) {
    asm("fma.rn.f32x2 %0, %1, %2, %0;" : "+l"(d) : "l"(a), "l"(b));
}
__device__ __forceinline__ unsigned long long pack2(float lo, float hi) {
    unsigned long long r; asm("mov.b64 %0, {%1, %2};" : "=l"(r) : "f"(lo), "f"(hi)); return r;
}
__device__ __forceinline__ float lo32(unsigned long long v){ return __uint_as_float((unsigned)(v & 0xffffffffull)); }
__device__ __forceinline__ float hi32(unsigned long long v){ return __uint_as_float((unsigned)(v >> 32)); }
__device__ __forceinline__ unsigned smem_u32(const void* p){ return (unsigned)__cvta_generic_to_shared(p); }
__device__ __forceinline__ unsigned mapa_rank(unsigned a, unsigned rk){
    unsigned r; asm("mapa.shared::cluster.u32 %0, %1, %2;" : "=r"(r) : "r"(a), "r"(rk)); return r;
}
__device__ __forceinline__ void cluster_sync_(){
    asm volatile("barrier.cluster.arrive.aligned;" ::: "memory");
    asm volatile("barrier.cluster.wait.aligned;" ::: "memory");
}
__device__ __forceinline__ float tanha(float x){
    float y; asm("tanh.approx.f32 %0, %1;" : "=f"(y) : "f"(x)); return y;
}
__device__ __forceinline__ float sig(float x){ return fmaf(0.5f, tanha(0.5f * x), 0.5f); }

__device__ __forceinline__ void mbar_init(unsigned bar, unsigned cnt){
    asm volatile("mbarrier.init.shared.b64 [%0], %1;" :: "r"(bar), "r"(cnt) : "memory");
}
__device__ __forceinline__ void mbar_arm(unsigned bar, unsigned tx){
    asm volatile("mbarrier.arrive.expect_tx.shared.b64 _, [%0], %1;" :: "r"(bar), "r"(tx) : "memory");
}
__device__ __forceinline__ void mbar_wait(unsigned bar, unsigned parity){
    asm volatile(
        "{\n\t.reg .pred P;\n\t"
        "WL_%=:\n\t"
        "mbarrier.try_wait.parity.acquire.cluster.shared::cta.b64 P, [%0], %1, 0x989680;\n\t"
        "@!P bra WL_%=;\n\t}"
        :: "r"(bar), "r"(parity) : "memory");
}
// remote 8-byte store + remote mbarrier tx-completion in one instruction
__device__ __forceinline__ void st_async_b64(unsigned raddr, unsigned rbar, unsigned long long v){
    asm volatile("st.async.shared::cluster.mbarrier::complete_tx::bytes.b64 [%0], %1, [%2];"
                 :: "r"(raddr), "l"(v), "r"(rbar) : "memory");
}
// bulk global->shared with mbarrier tx-completion (UBLKCP)
__device__ __forceinline__ void bulk_g2s(unsigned dst, const void* src, unsigned bytes, unsigned bar){
    asm volatile("cp.async.bulk.shared::cluster.global.mbarrier::complete_tx::bytes [%0], [%1], %2, [%3];"
                 :: "r"(dst), "l"(src), "r"(bytes), "r"(bar) : "memory");
}
// classic cp.async 16B
__device__ __forceinline__ void cp_async16(unsigned dst, const void* src){
    asm volatile("cp.async.cg.shared.global [%0], [%1], 16;" :: "r"(dst), "l"(src));
}
__device__ __forceinline__ void cp_commit(){ asm volatile("cp.async.commit_group;" ::: "memory"); }
__device__ __forceinline__ void cp_wait0(){ asm volatile("cp.async.wait_group 0;" ::: "memory"); }

// column permutation for g_zx: j (0..1023) -> jp
__device__ __forceinline__ int jperm(int col){
    return ((col >> 5) & 7) * 128 + (col >> 8) * 32 + (col & 31);
}

// ----------------------------- phase 1: Zx = x @ Wx + b (+ tail zeroing) -----------------------------
// Software-pipelined: B via cp.async (ping-pong), A via LDG->regs->STS overlap.
// One __syncthreads per 32-k chunk. f32x2-packed 8x8 microtile (4 row-pairs).
__global__ void __launch_bounds__(256, 2)
gemm_x_kernel(const float* __restrict__ x, const float* __restrict__ W, const float* __restrict__ bias,
              float* __restrict__ out, long long tail_start, long long tail_n)
{
    __shared__ float As[2][32][128];   // [buf][k][row]
    __shared__ float Bs[2][32][128];   // [buf][k][col]

    const int tid = threadIdx.x;

    if (blockIdx.x == 0 && blockIdx.y < 64) {
        long long i = (long long)blockIdx.y * 256 + tid;
        if (i < tail_n) out[tail_start + i] = 0.0f;
    }

    const int colTile = blockIdx.x * 128;
    const int rowTile = blockIdx.y * 128;
    const int tx = tid & 15, ty = tid >> 4;

    unsigned long long accp[4][8];   // [row-pair][col] = (acc[2i][j], acc[2i+1][j])
    #pragma unroll
    for (int i = 0; i < 4; i++)
        #pragma unroll
        for (int j = 0; j < 8; j++) accp[i][j] = 0ull;

    const int arow = tid >> 3;          // 0..31 (row group base)
    const int akk  = (tid & 7) * 4;     // k offset 0..28
    const int bkk  = tid >> 3;          // 0..31 (k row for B)
    const int bj   = (tid & 7) * 16;    // col offset (floats)

    // per-chunk loaders
    auto ldgA = [&](int k0, float4* ar){
        #pragma unroll
        for (int wv = 0; wv < 4; wv++) {
            int rr = rowTile + arow + wv * 32;
            int bb = rr & 31, ss = rr >> 5;
            ar[wv] = *(const float4*)&x[((size_t)bb * S_LEN + ss) * 256 + k0 + akk];
        }
    };
    auto stsA = [&](int buf, const float4* ar){
        #pragma unroll
        for (int wv = 0; wv < 4; wv++) {
            int row = arow + wv * 32;
            As[buf][akk + 0][row] = ar[wv].x; As[buf][akk + 1][row] = ar[wv].y;
            As[buf][akk + 2][row] = ar[wv].z; As[buf][akk + 3][row] = ar[wv].w;
        }
    };
    auto cpB = [&](int k0, int buf){
        #pragma unroll
        for (int wv = 0; wv < 4; wv++)
            cp_async16(smem_u32(&Bs[buf][bkk][bj + wv * 4]),
                       &W[(size_t)(k0 + bkk) * NCOL + colTile + bj + wv * 4]);
        cp_commit();
    };

    // prologue: chunk 0 -> buf 0
    {
        float4 ar[4];
        ldgA(0, ar);
        cpB(0, 0);
        stsA(0, ar);
        cp_wait0();
        __syncthreads();
    }

    int cur = 0;
    for (int chunk = 0; chunk < 8; chunk++) {
        float4 ar[4];
        const int nxt = cur ^ 1;
        if (chunk < 7) {
            ldgA((chunk + 1) * 32, ar);      // in flight during compute
            cpB((chunk + 1) * 32, nxt);
        }

        #pragma unroll
        for (int kk = 0; kk < 32; kk++) {
            ulonglong2 A0 = *(const ulonglong2*)&As[cur][kk][ty * 8];
            ulonglong2 A1 = *(const ulonglong2*)&As[cur][kk][ty * 8 + 4];
            float4 b0 = *(const float4*)&Bs[cur][kk][tx * 8];
            float4 b1 = *(const float4*)&Bs[cur][kk][tx * 8 + 4];
            unsigned long long ap[4] = {A0.x, A0.y, A1.x, A1.y};
            float bsv[8] = {b0.x, b0.y, b0.z, b0.w, b1.x, b1.y, b1.z, b1.w};
            #pragma unroll
            for (int j = 0; j < 8; j++) {
                unsigned long long bb = pack2(bsv[j], bsv[j]);
                #pragma unroll
                for (int i = 0; i < 4; i++) fma2(accp[i][j], ap[i], bb);
            }
        }

        if (chunk < 7) {
            stsA(nxt, ar);
            cp_wait0();
            __syncthreads();
            cur = nxt;
        }
    }

    float bv[8];
    #pragma unroll
    for (int j = 0; j < 8; j++) bv[j] = bias[colTile + tx * 8 + j];

    // epilogue: store to permuted column layout (two 16B stores per row)
    const int c0 = colTile + tx * 8;
    const int jp0 = jperm(c0);        // c0 % 32 in {0,8,16,24} -> both float4s stay in-block
    const int jp1 = jperm(c0 + 4);
    #pragma unroll
    for (int i = 0; i < 4; i++) {
        size_t rr0 = (size_t)rowTile + ty * 8 + 2 * i;
        float4 e0, e1, o0, o1;
        e0.x = lo32(accp[i][0]) + bv[0]; e0.y = lo32(accp[i][1]) + bv[1];
        e0.z = lo32(accp[i][2]) + bv[2]; e0.w = lo32(accp[i][3]) + bv[3];
        e1.x = lo32(accp[i][4]) + bv[4]; e1.y = lo32(accp[i][5]) + bv[5];
        e1.z = lo32(accp[i][6]) + bv[6]; e1.w = lo32(accp[i][7]) + bv[7];
        o0.x = hi32(accp[i][0]) + bv[0]; o0.y = hi32(accp[i][1]) + bv[1];
        o0.z = hi32(accp[i][2]) + bv[2]; o0.w = hi32(accp[i][3]) + bv[3];
        o1.x = hi32(accp[i][4]) + bv[4]; o1.y = hi32(accp[i][5]) + bv[5];
        o1.z = hi32(accp[i][6]) + bv[6]; o1.w = hi32(accp[i][7]) + bv[7];
        *(float4*)&g_zx[rr0 * NCOL + jp0]       = e0;
        *(float4*)&g_zx[rr0 * NCOL + jp1]       = e1;
        *(float4*)&g_zx[(rr0 + 1) * NCOL + jp0] = o0;
        *(float4*)&g_zx[(rr0 + 1) * NCOL + jp1] = o1;
    }
}

// ----------------------------- phase 2: the recurrence -----------------------------
// 16 clusters x 8 CTAs; cluster p owns chains 2p, 2p+1; CTA rank r owns units
// [r*32, r*32+32). Thread t = m*16 + ks (unit m, 16-k slice ks). Weights: 64
// f32x2 regs shared across chains. Butterfly reduce over ks; lanes 0/1/16/17
// finish one (chain, unit) tail; 16 lanes/warp send 8B h-pairs via st.async.
// zx arrives via cp.async.bulk issued 2 steps ahead by tid 511 (who also
// re-arms the barrier -> program-ordered), completing on the SAME ping-pong
// mbarrier (expect_tx = 2048 h + 1024 zx = 3072).
__global__ void __cluster_dims__(8, 1, 1) __launch_bounds__(512, 1)
lstm_chain_kernel(const float* __restrict__ W, const float* __restrict__ h0,
                  const float* __restrict__ c0, float* __restrict__ out)
{
    __shared__ __align__(16) float h_buf[2][2][HROW];   // [parity][chain][padded k]
    __shared__ __align__(16) float zx_s[4][2][128];     // [slot][chain][g*32+m]
    __shared__ __align__(8) unsigned long long mbar[2];

    const int tid  = threadIdx.x;
    const int p    = blockIdx.x >> 3;
    const int r    = blockIdx.x & 7;
    const int lane = tid & 31;

    const int m  = tid >> 4;     // 0..31 unit (local)
    const int ks = tid & 15;     // k-slice

    // ---- weights
    unsigned long long w2[32];
    {
        const float* Wb = W + (size_t)(256 + ks * 16) * NCOL + r * 32 + m;
        #pragma unroll
        for (int g = 0; g < 4; g++)
            #pragma unroll
            for (int q = 0; q < 8; q++)
                w2[g * 8 + q] = pack2(Wb[(size_t)(2 * q) * NCOL + g * 256],
                                      Wb[(size_t)(2 * q + 1) * NCOL + g * 256]);
    }

    const unsigned hb_base = smem_u32(&h_buf[0][0][0]);
    const unsigned mb_base = smem_u32(&mbar[0]);
    const int dMB = (int)(mb_base - hb_base);

    // zx source base for this CTA (contiguous 512B per chain per step)
    const float* zx_src = g_zx + (size_t)(2 * p) * NCOL + r * 128;
    const size_t zx_step = (size_t)BATCH * NCOL;   // floats per s

    if (tid == 511) {
        mbar_init(mb_base, 1);
        mbar_init(mb_base + 8, 1);
        mbar_arm(mb_base, 3072);      // waited at s=2: h(s=1) + zx(s=2)
        mbar_arm(mb_base + 8, 3072);  // waited at s=1: h(s=0) + zx(s=1)
        // prefetch zx for s=1 -> slot 1, completes on bar[1]
        bulk_g2s(smem_u32(&zx_s[1][0][0]), zx_src + 1 * zx_step,        512, mb_base + 8);
        bulk_g2s(smem_u32(&zx_s[1][1][0]), zx_src + 1 * zx_step + NCOL, 512, mb_base + 8);
    }

    // ---- init h_buf[0]
    {
        int ch = tid >> 8, k = tid & 255;
        h_buf[0][ch][k + ((k >> 4) << 2)] = h0[(size_t)(2 * p + ch) * HID + k];
    }

    // ---- owner lanes (ks<2): chain myc, unit m; preload zx for s=0 directly
    const int myc = ks;
    float cst = 0.0f;
    float zx0v[4];
    if (ks < 2) {
        cst = c0[(size_t)(2 * p + myc) * HID + r * 32 + m];
        #pragma unroll
        for (int g = 0; g < 4; g++)
            zx0v[g] = __ldg(zx_src + (size_t)myc * NCOL + g * 32 + m);
    }

    unsigned hmap[8];
    #pragma unroll
    for (int rk = 0; rk < 8; rk++) hmap[rk] = mapa_rank(hb_base, rk);

    const int m0  = 2 * (tid >> 5);            // even unit of this warp
    const int kg0 = r * 32 + m0;
    const int po0 = kg0 + ((kg0 >> 4) << 2);   // padded offset (8B aligned)

    float* out_base = out + ((size_t)(2 * p + (ks < 2 ? myc : 0)) * S_LEN) * HID + r * 32 + m;

    const bool sender = (lane < 8) || (lane >= 16 && lane < 24);
    const int  s_ch   = (lane < 8) ? 0 : 1;
    const int  s_rk   = lane & 7;

    __syncthreads();
    cluster_sync_();   // barriers armed + h_buf[0] ready cluster-wide

    int ph0 = 0, ph1 = 0;

    for (int s = 0; s < S_LEN; s++) {
        const int par = s & 1;

        if (s > 0) {
            unsigned bar = mb_base + (unsigned)par * 8;
            int ph = par ? ph1 : ph0;
            mbar_wait(bar, (unsigned)ph);
            if (par) ph1 ^= 1; else ph0 ^= 1;
            if (tid == 511) {
                mbar_arm(bar, 3072);                     // phase used at s+2
                if (s + 2 < S_LEN) {                     // zx(s+2) -> same barrier
                    const int slot = (s + 2) & 3;
                    const float* src = zx_src + (size_t)(s + 2) * zx_step;
                    bulk_g2s(smem_u32(&zx_s[slot][0][0]), src,        512, bar);
                    bulk_g2s(smem_u32(&zx_s[slot][1][0]), src + NCOL, 512, bar);
                }
            }
        } else {
            if (tid == 511) {   // zx(2) -> bar[0] (pre-armed 3072)
                bulk_g2s(smem_u32(&zx_s[2][0][0]), zx_src + 2 * zx_step,        512, mb_base);
                bulk_g2s(smem_u32(&zx_s[2][1][0]), zx_src + 2 * zx_step + NCOL, 512, mb_base);
            }
        }

        // ---- Wh . h over this thread's 16-k slice, 4 gates, 2 chains
        unsigned long long accA[4] = {0,0,0,0}, accB[4] = {0,0,0,0};
        {
            const ulonglong2* hb = (const ulonglong2*)&h_buf[par][0][ks * 20];
            ulonglong2 q0 = hb[0], q1 = hb[1], q2 = hb[2], q3 = hb[3];
            unsigned long long h8[8] = {q0.x, q0.y, q1.x, q1.y, q2.x, q2.y, q3.x, q3.y};
            #pragma unroll
            for (int g = 0; g < 4; g++)
                #pragma unroll
                for (int q = 0; q < 8; q++) fma2(accA[g], w2[g * 8 + q], h8[q]);
        }
        {
            const ulonglong2* hb = (const ulonglong2*)&h_buf[par][1][ks * 20];
            ulonglong2 q0 = hb[0], q1 = hb[1], q2 = hb[2], q3 = hb[3];
            unsigned long long h8[8] = {q0.x, q0.y, q1.x, q1.y, q2.x, q2.y, q3.x, q3.y};
            #pragma unroll
            for (int g = 0; g < 4; g++)
                #pragma unroll
                for (int q = 0; q < 8; q++) fma2(accB[g], w2[g * 8 + q], h8[q]);
        }

        float sv[8];
        #pragma unroll
        for (int g = 0; g < 4; g++) {
            sv[g]     = lo32(accA[g]) + hi32(accA[g]);
            sv[4 + g] = lo32(accB[g]) + hi32(accB[g]);
        }
        #pragma unroll
        for (int v = 0; v < 8; v++) {
            sv[v] += __shfl_xor_sync(0xffffffffu, sv[v], 1);
            sv[v] += __shfl_xor_sync(0xffffffffu, sv[v], 2);
            sv[v] += __shfl_xor_sync(0xffffffffu, sv[v], 4);
            sv[v] += __shfl_xor_sync(0xffffffffu, sv[v], 8);
        }

        // ---- per-lane tail (lanes 0/1/16/17)
        float hn = 0.0f;
        if (ks < 2) {
            float zx0, zx1, zx2, zx3;
            if (s == 0) { zx0 = zx0v[0]; zx1 = zx0v[1]; zx2 = zx0v[2]; zx3 = zx0v[3]; }
            else {
                const float* zr = &zx_s[s & 3][myc][m];
                zx0 = zr[0]; zx1 = zr[32]; zx2 = zr[64]; zx3 = zr[96];
            }
            float zi = tanha(sv[myc * 4 + 0] + zx0);
            float zf = tanha(sv[myc * 4 + 1] + zx1);
            float zg = tanha(sv[myc * 4 + 2] + zx2);
            float zo = tanha(sv[myc * 4 + 3] + zx3);
            cst = sig(zf) * cst + sig(zi) * tanha(zg);
            hn  = tanha(cst) * sig(zo);
        }

        float he0 = __shfl_sync(0xffffffffu, hn, 0);
        float he1 = __shfl_sync(0xffffffffu, hn, 1);
        float ho0 = __shfl_sync(0xffffffffu, hn, 16);
        float ho1 = __shfl_sync(0xffffffffu, hn, 17);

        if (sender && (s + 1 < S_LEN)) {
            const int parN = par ^ 1;
            unsigned long long pv = (s_ch == 0) ? pack2(he0, ho0) : pack2(he1, ho1);
            unsigned off = (unsigned)(((parN * 2 + s_ch) * HROW + po0) * 4);
            unsigned mbo = (unsigned)(dMB + parN * 8);
            st_async_b64(hmap[s_rk] + off, hmap[s_rk] + mbo, pv);
        }

        if (ks < 2)
            out_base[(size_t)s * HID] = hn;
    }

    // no CTA may exit while peers could still have remote stores in flight
    cluster_sync_();
}

// ----------------------------- launcher -----------------------------
extern "C" void kernel_launch(void* const* d_in, const int* in_sizes, int n_in,
                              void* d_out, int out_size) {
    const float* x    = (const float*)d_in[0];   // (32, 2048, 256)
    const float* h0   = (const float*)d_in[1];   // (1, 32, 256)
    const float* c0   = (const float*)d_in[2];   // (1, 32, 256)
    const float* W    = (const float*)d_in[3];   // (512, 1024)
    const float* bias = (const float*)d_in[4];   // (1024,)
    float* out = (float*)d_out;

    const long long main_elems = (long long)BATCH * S_LEN * HID;
    const long long tail = (long long)out_size - main_elems;

    gemm_x_kernel<<<dim3(8, 512, 1), 256>>>(x, W, bias, out, main_elems, tail > 0 ? tail : 0);
    lstm_chain_kernel<<<128, 512>>>(W, h0, c0, out);
}

// round 12
// speedup vs baseline: 1.5166x; 1.1971x over previous
#include <cuda_runtime.h>
#include <cstdint>

#define S_LEN 2048
#define BATCH 32
#define HID   256
#define NCOL  1024   // 4*H
#define HROW  320    // 256 + 4-float pad per 16 floats (conflict-free LDS phases)

// 256 MB scratch for Zx = x @ Wx + b.
// Layout: [s][b][jp], jp = r*128 + g*32 + m  -> per-CTA per-chain step slice is
// one contiguous 512B block (cp.async.bulk friendly).
__device__ float g_zx[(size_t)S_LEN * BATCH * NCOL];

// ----------------------------- helpers -----------------------------
__device__ __forceinline__ void fma2(unsigned long long &d, unsigned long long a, unsigned long long b) {
    asm("fma.rn.f32x2 %0, %1, %2, %0;" : "+l"(d) : "l"(a), "l"(b));
}
__device__ __forceinline__ unsigned long long pack2(float lo, float hi) {
    unsigned long long r; asm("mov.b64 %0, {%1, %2};" : "=l"(r) : "f"(lo), "f"(hi)); return r;
}
__device__ __forceinline__ float lo32(unsigned long long v){ return __uint_as_float((unsigned)(v & 0xffffffffull)); }
__device__ __forceinline__ float hi32(unsigned long long v){ return __uint_as_float((unsigned)(v >> 32)); }
__device__ __forceinline__ unsigned smem_u32(const void* p){ return (unsigned)__cvta_generic_to_shared(p); }
__device__ __forceinline__ unsigned mapa_rank(unsigned a, unsigned rk){
    unsigned r; asm("mapa.shared::cluster.u32 %0, %1, %2;" : "=r"(r) : "r"(a), "r"(rk)); return r;
}
__device__ __forceinline__ void cluster_sync_(){
    asm volatile("barrier.cluster.arrive.aligned;" ::: "memory");
    asm volatile("barrier.cluster.wait.aligned;" ::: "memory");
}
__device__ __forceinline__ float tanha(float x){
    float y; asm("tanh.approx.f32 %0, %1;" : "=f"(y) : "f"(x)); return y;
}
__device__ __forceinline__ float sig(float x){ return fmaf(0.5f, tanha(0.5f * x), 0.5f); }

__device__ __forceinline__ void mbar_init(unsigned bar, unsigned cnt){
    asm volatile("mbarrier.init.shared.b64 [%0], %1;" :: "r"(bar), "r"(cnt) : "memory");
}
__device__ __forceinline__ void mbar_arm(unsigned bar, unsigned tx){
    asm volatile("mbarrier.arrive.expect_tx.shared.b64 _, [%0], %1;" :: "r"(bar), "r"(tx) : "memory");
}
__device__ __forceinline__ void mbar_wait(unsigned bar, unsigned parity){
    asm volatile(
        "{\n\t.reg .pred P;\n\t"
        "WL_%=:\n\t"
        "mbarrier.try_wait.parity.acquire.cluster.shared::cta.b64 P, [%0], %1, 0x989680;\n\t"
        "@!P bra WL_%=;\n\t}"
        :: "r"(bar), "r"(parity) : "memory");
}
__device__ __forceinline__ void st_async_b64(unsigned raddr, unsigned rbar, unsigned long long v){
    asm volatile("st.async.shared::cluster.mbarrier::complete_tx::bytes.b64 [%0], %1, [%2];"
                 :: "r"(raddr), "l"(v), "r"(rbar) : "memory");
}
__device__ __forceinline__ void bulk_g2s(unsigned dst, const void* src, unsigned bytes, unsigned bar){
    asm volatile("cp.async.bulk.shared::cluster.global.mbarrier::complete_tx::bytes [%0], [%1], %2, [%3];"
                 :: "r"(dst), "l"(src), "r"(bytes), "r"(bar) : "memory");
}
__device__ __forceinline__ void cp_async16(unsigned dst, const void* src){
    asm volatile("cp.async.cg.shared.global [%0], [%1], 16;" :: "r"(dst), "l"(src));
}
__device__ __forceinline__ void cp_commit(){ asm volatile("cp.async.commit_group;" ::: "memory"); }
__device__ __forceinline__ void cp_wait0(){ asm volatile("cp.async.wait_group 0;" ::: "memory"); }

__device__ __forceinline__ int jperm(int col){
    return ((col >> 5) & 7) * 128 + (col >> 8) * 32 + (col & 31);
}

// ----------------------------- phase 1: Zx = x @ Wx + b (+ tail zeroing) -----------------------------
// Software-pipelined (unchanged from R9): B via cp.async ping-pong, A via
// LDG->regs->STS overlap, one __syncthreads per 32-k chunk, f32x2 microtile.
__global__ void __launch_bounds__(256, 2)
gemm_x_kernel(const float* __restrict__ x, const float* __restrict__ W, const float* __restrict__ bias,
              float* __restrict__ out, long long tail_start, long long tail_n)
{
    __shared__ float As[2][32][128];
    __shared__ float Bs[2][32][128];

    const int tid = threadIdx.x;

    if (blockIdx.x == 0 && blockIdx.y < 64) {
        long long i = (long long)blockIdx.y * 256 + tid;
        if (i < tail_n) out[tail_start + i] = 0.0f;
    }

    const int colTile = blockIdx.x * 128;
    const int rowTile = blockIdx.y * 128;
    const int tx = tid & 15, ty = tid >> 4;

    unsigned long long accp[4][8];
    #pragma unroll
    for (int i = 0; i < 4; i++)
        #pragma unroll
        for (int j = 0; j < 8; j++) accp[i][j] = 0ull;

    const int arow = tid >> 3;
    const int akk  = (tid & 7) * 4;
    const int bkk  = tid >> 3;
    const int bj   = (tid & 7) * 16;

    auto ldgA = [&](int k0, float4* ar){
        #pragma unroll
        for (int wv = 0; wv < 4; wv++) {
            int rr = rowTile + arow + wv * 32;
            int bb = rr & 31, ss = rr >> 5;
            ar[wv] = *(const float4*)&x[((size_t)bb * S_LEN + ss) * 256 + k0 + akk];
        }
    };
    auto stsA = [&](int buf, const float4* ar){
        #pragma unroll
        for (int wv = 0; wv < 4; wv++) {
            int row = arow + wv * 32;
            As[buf][akk + 0][row] = ar[wv].x; As[buf][akk + 1][row] = ar[wv].y;
            As[buf][akk + 2][row] = ar[wv].z; As[buf][akk + 3][row] = ar[wv].w;
        }
    };
    auto cpB = [&](int k0, int buf){
        #pragma unroll
        for (int wv = 0; wv < 4; wv++)
            cp_async16(smem_u32(&Bs[buf][bkk][bj + wv * 4]),
                       &W[(size_t)(k0 + bkk) * NCOL + colTile + bj + wv * 4]);
        cp_commit();
    };

    {
        float4 ar[4];
        ldgA(0, ar);
        cpB(0, 0);
        stsA(0, ar);
        cp_wait0();
        __syncthreads();
    }

    int cur = 0;
    for (int chunk = 0; chunk < 8; chunk++) {
        float4 ar[4];
        const int nxt = cur ^ 1;
        if (chunk < 7) {
            ldgA((chunk + 1) * 32, ar);
            cpB((chunk + 1) * 32, nxt);
        }

        #pragma unroll
        for (int kk = 0; kk < 32; kk++) {
            ulonglong2 A0 = *(const ulonglong2*)&As[cur][kk][ty * 8];
            ulonglong2 A1 = *(const ulonglong2*)&As[cur][kk][ty * 8 + 4];
            float4 b0 = *(const float4*)&Bs[cur][kk][tx * 8];
            float4 b1 = *(const float4*)&Bs[cur][kk][tx * 8 + 4];
            unsigned long long ap[4] = {A0.x, A0.y, A1.x, A1.y};
            float bsv[8] = {b0.x, b0.y, b0.z, b0.w, b1.x, b1.y, b1.z, b1.w};
            #pragma unroll
            for (int j = 0; j < 8; j++) {
                unsigned long long bb = pack2(bsv[j], bsv[j]);
                #pragma unroll
                for (int i = 0; i < 4; i++) fma2(accp[i][j], ap[i], bb);
            }
        }

        if (chunk < 7) {
            stsA(nxt, ar);
            cp_wait0();
            __syncthreads();
            cur = nxt;
        }
    }

    float bv[8];
    #pragma unroll
    for (int j = 0; j < 8; j++) bv[j] = bias[colTile + tx * 8 + j];

    const int c0 = colTile + tx * 8;
    const int jp0 = jperm(c0);
    const int jp1 = jperm(c0 + 4);
    #pragma unroll
    for (int i = 0; i < 4; i++) {
        size_t rr0 = (size_t)rowTile + ty * 8 + 2 * i;
        float4 e0, e1, o0, o1;
        e0.x = lo32(accp[i][0]) + bv[0]; e0.y = lo32(accp[i][1]) + bv[1];
        e0.z = lo32(accp[i][2]) + bv[2]; e0.w = lo32(accp[i][3]) + bv[3];
        e1.x = lo32(accp[i][4]) + bv[4]; e1.y = lo32(accp[i][5]) + bv[5];
        e1.z = lo32(accp[i][6]) + bv[6]; e1.w = lo32(accp[i][7]) + bv[7];
        o0.x = hi32(accp[i][0]) + bv[0]; o0.y = hi32(accp[i][1]) + bv[1];
        o0.z = hi32(accp[i][2]) + bv[2]; o0.w = hi32(accp[i][3]) + bv[3];
        o1.x = hi32(accp[i][4]) + bv[4]; o1.y = hi32(accp[i][5]) + bv[5];
        o1.z = hi32(accp[i][6]) + bv[6]; o1.w = hi32(accp[i][7]) + bv[7];
        *(float4*)&g_zx[rr0 * NCOL + jp0]       = e0;
        *(float4*)&g_zx[rr0 * NCOL + jp1]       = e1;
        *(float4*)&g_zx[(rr0 + 1) * NCOL + jp0] = o0;
        *(float4*)&g_zx[(rr0 + 1) * NCOL + jp1] = o1;
    }
}

// ----------------------------- phase 2: the recurrence -----------------------------
// 16 clusters x 8 CTAs; cluster p owns chains 2p,2p+1; rank r owns units
// [r*32,r*32+32). Thread t = m*16+ks. Value-splitting butterfly (8 shfls) ends
// with lane ks holding the reduced sum for v=ks&7 (chain=bit2, gate=bits0-1).
// Distributed tail: each lane 1 pre-activation tanh + per-gate nonlinearity;
// 2 shfl_xor combine into f-lanes (cst/hn owners); senders (lanes 0-7 chain0,
// 16-23 chain1) gather the unit pair via 2 shfl.idx and push one 8B st.async
// to their rank. Warp 0 waits the mbarrier; others park at __syncthreads.
__global__ void __cluster_dims__(8, 1, 1) __launch_bounds__(512, 1)
lstm_chain_kernel(const float* __restrict__ W, const float* __restrict__ h0,
                  const float* __restrict__ c0, float* __restrict__ out)
{
    __shared__ __align__(16) float h_buf[2][2][HROW];   // [parity][chain][padded k]
    __shared__ __align__(16) float zx_s[4][2][128];     // [slot][chain][g*32+m]
    __shared__ __align__(8) unsigned long long mbar[2];

    const int tid  = threadIdx.x;
    const int p    = blockIdx.x >> 3;
    const int r    = blockIdx.x & 7;
    const int lane = tid & 31;

    const int m  = tid >> 4;     // 0..31 unit (local)
    const int ks = tid & 15;     // k-slice

    // ---- weights: w2[g*8+q] covers k = ks*16 + 2q,2q+1, col = g*256 + r*32 + m
    unsigned long long w2[32];
    {
        const float* Wb = W + (size_t)(256 + ks * 16) * NCOL + r * 32 + m;
        #pragma unroll
        for (int g = 0; g < 4; g++)
            #pragma unroll
            for (int q = 0; q < 8; q++)
                w2[g * 8 + q] = pack2(Wb[(size_t)(2 * q) * NCOL + g * 256],
                                      Wb[(size_t)(2 * q + 1) * NCOL + g * 256]);
    }

    const unsigned hb_base = smem_u32(&h_buf[0][0][0]);
    const unsigned mb_base = smem_u32(&mbar[0]);
    const int dMB = (int)(mb_base - hb_base);

    const float* zx_src = g_zx + (size_t)(2 * p) * NCOL + r * 128;
    const size_t zx_step = (size_t)BATCH * NCOL;

    if (tid == 511) {
        mbar_init(mb_base, 1);
        mbar_init(mb_base + 8, 1);
        mbar_arm(mb_base, 3072);      // waited at s=2: h(s=1) + zx(s=2)
        mbar_arm(mb_base + 8, 3072);  // waited at s=1: h(s=0) + zx(s=1)
        bulk_g2s(smem_u32(&zx_s[1][0][0]), zx_src + 1 * zx_step,        512, mb_base + 8);
        bulk_g2s(smem_u32(&zx_s[1][1][0]), zx_src + 1 * zx_step + NCOL, 512, mb_base + 8);
    }

    // ---- init h_buf[0]
    {
        int ch = tid >> 8, k = tid & 255;
        h_buf[0][ch][k + ((k >> 4) << 2)] = h0[(size_t)(2 * p + ch) * HID + k];
    }

    // ---- lane roles from v = ks&7
    const int v_ch   = (ks >> 2) & 1;   // chain of my reduced value
    const int v_gate = ks & 3;          // gate of my reduced value
    const bool owner = (v_gate == 1) && (ks < 8);   // lanes 1,5 (+16: 17,21)

    // cst at f-lanes (all dups maintain identical copies)
    float cst = 0.0f;
    if (v_gate == 1) cst = c0[(size_t)(2 * p + v_ch) * HID + r * 32 + m];

    // zx for s=0 (one value per lane)
    float zx0v = __ldg(zx_src + (size_t)v_ch * NCOL + v_gate * 32 + m);

    unsigned hmap[8];
    #pragma unroll
    for (int rk = 0; rk < 8; rk++) hmap[rk] = mapa_rank(hb_base, rk);

    const int m0  = 2 * (tid >> 5);            // even unit of this warp
    const int kg0 = r * 32 + m0;
    const int po0 = kg0 + ((kg0 >> 4) << 2);   // padded offset (8B aligned)

    // out pointer for owner lanes (unit m, chain v_ch); stepped by +HID
    float* out_ptr = out + ((size_t)(2 * p + v_ch) * S_LEN) * HID + r * 32 + m;

    // sender role: lanes 0-7 -> chain0 to rank lane; 16-23 -> chain1 to rank lane-16
    const bool sender = (lane < 8) || (lane >= 16 && lane < 24);
    const int  s_ch   = (lane < 8) ? 0 : 1;
    const int  s_rk   = lane & 7;
    const int  srcA   = s_ch ? 5 : 1;          // hn source lanes (even unit)
    const int  srcB   = srcA + 16;             // (odd unit)

    const bool b0 = (ks & 1), b1 = (ks >> 1) & 1, b2 = (ks >> 2) & 1;

    __syncthreads();
    cluster_sync_();   // barriers armed + h_buf[0] ready cluster-wide

    int ph0 = 0, ph1 = 0;

    for (int s = 0; s < S_LEN; s++) {
        const int par = s & 1;

        if (s > 0) {
            unsigned bar = mb_base + (unsigned)par * 8;
            int ph = par ? ph1 : ph0;
            if (tid < 32) mbar_wait(bar, (unsigned)ph);   // warp 0 polls; rest park
            if (par) ph1 ^= 1; else ph0 ^= 1;
            __syncthreads();
            if (tid == 511) {
                mbar_arm(bar, 3072);                      // phase used at s+2
                if (s + 2 < S_LEN) {
                    const int slot = (s + 2) & 3;
                    const float* src = zx_src + (size_t)(s + 2) * zx_step;
                    bulk_g2s(smem_u32(&zx_s[slot][0][0]), src,        512, bar);
                    bulk_g2s(smem_u32(&zx_s[slot][1][0]), src + NCOL, 512, bar);
                }
            }
        } else {
            if (tid == 511) {
                bulk_g2s(smem_u32(&zx_s[2][0][0]), zx_src + 2 * zx_step,        512, mb_base);
                bulk_g2s(smem_u32(&zx_s[2][1][0]), zx_src + 2 * zx_step + NCOL, 512, mb_base);
            }
        }

        // ---- Wh . h over this thread's 16-k slice, 4 gates, 2 chains
        unsigned long long accA[4] = {0,0,0,0}, accB[4] = {0,0,0,0};
        {
            const ulonglong2* hb = (const ulonglong2*)&h_buf[par][0][ks * 20];
            ulonglong2 q0 = hb[0], q1 = hb[1], q2 = hb[2], q3 = hb[3];
            unsigned long long h8[8] = {q0.x, q0.y, q1.x, q1.y, q2.x, q2.y, q3.x, q3.y};
            #pragma unroll
            for (int g = 0; g < 4; g++)
                #pragma unroll
                for (int q = 0; q < 8; q++) fma2(accA[g], w2[g * 8 + q], h8[q]);
        }
        {
            const ulonglong2* hb = (const ulonglong2*)&h_buf[par][1][ks * 20];
            ulonglong2 q0 = hb[0], q1 = hb[1], q2 = hb[2], q3 = hb[3];
            unsigned long long h8[8] = {q0.x, q0.y, q1.x, q1.y, q2.x, q2.y, q3.x, q3.y};
            #pragma unroll
            for (int g = 0; g < 4; g++)
                #pragma unroll
                for (int q = 0; q < 8; q++) fma2(accB[g], w2[g * 8 + q], h8[q]);
        }

        float sv[8];
        #pragma unroll
        for (int g = 0; g < 4; g++) {
            sv[g]     = lo32(accA[g]) + hi32(accA[g]);
            sv[4 + g] = lo32(accB[g]) + hi32(accB[g]);
        }

        // ---- value-splitting butterfly over ks (8 shfls, static indices)
        float k0v[4], k1v[2], k2v;
        #pragma unroll
        for (int j = 0; j < 4; j++) {
            float snd = b0 ? sv[2 * j] : sv[2 * j + 1];
            float rcv = __shfl_xor_sync(0xffffffffu, snd, 1);
            k0v[j] = (b0 ? sv[2 * j + 1] : sv[2 * j]) + rcv;
        }
        #pragma unroll
        for (int j = 0; j < 2; j++) {
            float snd = b1 ? k0v[2 * j] : k0v[2 * j + 1];
            float rcv = __shfl_xor_sync(0xffffffffu, snd, 2);
            k1v[j] = (b1 ? k0v[2 * j + 1] : k0v[2 * j]) + rcv;
        }
        {
            float snd = b2 ? k1v[0] : k1v[1];
            float rcv = __shfl_xor_sync(0xffffffffu, snd, 4);
            k2v = (b2 ? k1v[1] : k1v[0]) + rcv;
        }
        float F = k2v + __shfl_xor_sync(0xffffffffu, k2v, 8);
        // lane now holds the full sum for (chain=v_ch, gate=v_gate, unit m)

        // ---- distributed tail
        float zx = (s == 0) ? zx0v : zx_s[s & 3][v_ch][v_gate * 32 + m];
        float t = tanha(F + zx);
        // a = gate==2 ? tanh(t) : sigmoid(t)
        float u = (v_gate == 2) ? t : 0.5f * t;
        float w = tanha(u);
        float a = (v_gate == 2) ? w : fmaf(0.5f, w, 0.5f);

        float ax = __shfl_xor_sync(0xffffffffu, a, 2);  // gate0<-a_g, gate1<-a_o
        float P  = a * ax;                               // at gate0: a_i * a_g
        float Pr = __shfl_xor_sync(0xffffffffu, P, 1);  // gate1 <- gate0's P

        float hn = 0.0f;
        if (v_gate == 1) {            // f-lanes own cst (dups identical)
            cst = a * cst + Pr;       // f*c + i*g
            hn  = tanha(cst) * ax;    // tanh(c) * o
        }

        // gather unit-pair hn to senders (2 shfl.idx; hn at lanes 1/5/17/21)
        float hA = __shfl_sync(0xffffffffu, hn, srcA);
        float hB = __shfl_sync(0xffffffffu, hn, srcB);

        if (sender && (s + 1 < S_LEN)) {
            const int parN = par ^ 1;
            unsigned long long pv = pack2(hA, hB);
            unsigned off = (unsigned)(((parN * 2 + s_ch) * HROW + po0) * 4);
            unsigned mbo = (unsigned)(dMB + parN * 8);
            st_async_b64(hmap[s_rk] + off, hmap[s_rk] + mbo, pv);
        }

        if (owner)
            out_ptr[0] = hn;
        out_ptr += HID;
    }

    cluster_sync_();   // no CTA exits while remote stores may be in flight
}

// ----------------------------- launcher -----------------------------
extern "C" void kernel_launch(void* const* d_in, const int* in_sizes, int n_in,
                              void* d_out, int out_size) {
    const float* x    = (const float*)d_in[0];   // (32, 2048, 256)
    const float* h0   = (const float*)d_in[1];   // (1, 32, 256)
    const float* c0   = (const float*)d_in[2];   // (1, 32, 256)
    const float* W    = (const float*)d_in[3];   // (512, 1024)
    const float* bias = (const float*)d_in[4];   // (1024,)
    float* out = (float*)d_out;

    const long long main_elems = (long long)BATCH * S_LEN * HID;
    const long long tail = (long long)out_size - main_elems;

    gemm_x_kernel<<<dim3(8, 512, 1), 256>>>(x, W, bias, out, main_elems, tail > 0 ? tail : 0);
    lstm_chain_kernel<<<128, 512>>>(W, h0, c0, out);
}

// round 13
// speedup vs baseline: 1.6933x; 1.1166x over previous
#include <cuda_runtime.h>
#include <cstdint>

#define S_LEN 2048
#define BATCH 32
#define HID   256
#define NCOL  1024   // 4*H
#define HROW  320    // 256 + 4-float pad per 16 floats (conflict-free LDS phases)

// 256 MB scratch for Zx = x @ Wx + b.
// Layout: [s][b][jp], jp = r*128 + g*32 + m  -> per-CTA per-chain step slice is
// one contiguous 512B block (cp.async.bulk friendly).
__device__ float g_zx[(size_t)S_LEN * BATCH * NCOL];

// ----------------------------- helpers -----------------------------
__device__ __forceinline__ void fma2(unsigned long long &d, unsigned long long a, unsigned long long b) {
    asm("fma.rn.f32x2 %0, %1, %2, %0;" : "+l"(d) : "l"(a), "l"(b));
}
__device__ __forceinline__ unsigned long long pack2(float lo, float hi) {
    unsigned long long r; asm("mov.b64 %0, {%1, %2};" : "=l"(r) : "f"(lo), "f"(hi)); return r;
}
__device__ __forceinline__ float lo32(unsigned long long v){ return __uint_as_float((unsigned)(v & 0xffffffffull)); }
__device__ __forceinline__ float hi32(unsigned long long v){ return __uint_as_float((unsigned)(v >> 32)); }
__device__ __forceinline__ unsigned smem_u32(const void* p){ return (unsigned)__cvta_generic_to_shared(p); }
__device__ __forceinline__ unsigned mapa_rank(unsigned a, unsigned rk){
    unsigned r; asm("mapa.shared::cluster.u32 %0, %1, %2;" : "=r"(r) : "r"(a), "r"(rk)); return r;
}
__device__ __forceinline__ void cluster_sync_(){
    asm volatile("barrier.cluster.arrive.aligned;" ::: "memory");
    asm volatile("barrier.cluster.wait.aligned;" ::: "memory");
}
__device__ __forceinline__ float tanha(float x){
    float y; asm("tanh.approx.f32 %0, %1;" : "=f"(y) : "f"(x)); return y;
}
__device__ __forceinline__ float sig(float x){ return fmaf(0.5f, tanha(0.5f * x), 0.5f); }

__device__ __forceinline__ void mbar_init(unsigned bar, unsigned cnt){
    asm volatile("mbarrier.init.shared.b64 [%0], %1;" :: "r"(bar), "r"(cnt) : "memory");
}
__device__ __forceinline__ void mbar_arm(unsigned bar, unsigned tx){
    asm volatile("mbarrier.arrive.expect_tx.shared.b64 _, [%0], %1;" :: "r"(bar), "r"(tx) : "memory");
}
__device__ __forceinline__ void mbar_wait(unsigned bar, unsigned parity){
    asm volatile(
        "{\n\t.reg .pred P;\n\t"
        "WL_%=:\n\t"
        "mbarrier.try_wait.parity.acquire.cluster.shared::cta.b64 P, [%0], %1, 0x989680;\n\t"
        "@!P bra WL_%=;\n\t}"
        :: "r"(bar), "r"(parity) : "memory");
}
__device__ __forceinline__ void st_async_b64(unsigned raddr, unsigned rbar, unsigned long long v){
    asm volatile("st.async.shared::cluster.mbarrier::complete_tx::bytes.b64 [%0], %1, [%2];"
                 :: "r"(raddr), "l"(v), "r"(rbar) : "memory");
}
__device__ __forceinline__ void bulk_g2s(unsigned dst, const void* src, unsigned bytes, unsigned bar){
    asm volatile("cp.async.bulk.shared::cluster.global.mbarrier::complete_tx::bytes [%0], [%1], %2, [%3];"
                 :: "r"(dst), "l"(src), "r"(bytes), "r"(bar) : "memory");
}
__device__ __forceinline__ void cp_async16(unsigned dst, const void* src){
    asm volatile("cp.async.cg.shared.global [%0], [%1], 16;" :: "r"(dst), "l"(src));
}
__device__ __forceinline__ void cp_commit(){ asm volatile("cp.async.commit_group;" ::: "memory"); }
__device__ __forceinline__ void cp_wait0(){ asm volatile("cp.async.wait_group 0;" ::: "memory"); }

__device__ __forceinline__ int jperm(int col){
    return ((col >> 5) & 7) * 128 + (col >> 8) * 32 + (col & 31);
}

__device__ __forceinline__ unsigned tf32_(float f){
    unsigned r; asm("cvt.rna.tf32.f32 %0, %1;" : "=r"(r) : "f"(f)); return r;
}
__device__ __forceinline__ void mma1688(float* d, const unsigned* a, unsigned b0, unsigned b1){
    asm("mma.sync.aligned.m16n8k8.row.col.f32.tf32.tf32.f32 "
        "{%0,%1,%2,%3}, {%4,%5,%6,%7}, {%8,%9}, {%0,%1,%2,%3};"
        : "+f"(d[0]), "+f"(d[1]), "+f"(d[2]), "+f"(d[3])
        : "r"(a[0]), "r"(a[1]), "r"(a[2]), "r"(a[3]), "r"(b0), "r"(b1));
}

// ----------------------------- phase 1: Zx = x @ Wx + b (tf32 tensor cores) -----------------------------
// 128x128 tile, 8 warps (warp-tile 32x64), K=16 double-buffered chunks fed by
// cp.async for BOTH operands. Bank-engineered strides: As[128][20] (a-frag
// banks = gid*4+tig, all distinct), Bs[16][136] (b-frag banks = tig*8+gid).
__global__ void __launch_bounds__(256)
gemm_x_kernel(const float* __restrict__ x, const float* __restrict__ W, const float* __restrict__ bias,
              float* __restrict__ out, long long tail_start, long long tail_n)
{
    __shared__ float As[2][128][20];   // [buf][row][k]  (stride 20: conflict-free frags)
    __shared__ float Bs[2][16][136];   // [buf][k][col]  (stride 136)

    const int tid = threadIdx.x;

    if (blockIdx.x == 0 && blockIdx.y < 64) {
        long long i = (long long)blockIdx.y * 256 + tid;
        if (i < tail_n) out[tail_start + i] = 0.0f;
    }

    const int colTile = blockIdx.x * 128;
    const int rowTile = blockIdx.y * 128;

    const int wid = tid >> 5, lane = tid & 31;
    const int wm = wid & 3;         // m-tile: rows wm*32..+32
    const int wn = wid >> 2;        // n-tile: cols wn*64..+64
    const int gid = lane >> 2;      // 0..7
    const int tig = lane & 3;       // 0..3

    float d[2][8][4];
    #pragma unroll
    for (int f = 0; f < 2; f++)
        #pragma unroll
        for (int j = 0; j < 8; j++)
            #pragma unroll
            for (int q = 0; q < 4; q++) d[f][j][q] = 0.0f;

    auto loadA = [&](int k0, int buf){
        #pragma unroll
        for (int j = 0; j < 2; j++){
            int i = tid * 2 + j;            // 0..511
            int row = i >> 2, seg = i & 3;  // 4 x 16B per 64B row-chunk
            int rr = rowTile + row;
            int bb = rr & 31, ss = rr >> 5;
            cp_async16(smem_u32(&As[buf][row][seg * 4]),
                       &x[((size_t)bb * S_LEN + ss) * 256 + k0 + seg * 4]);
        }
    };
    auto loadB = [&](int k0, int buf){
        #pragma unroll
        for (int j = 0; j < 2; j++){
            int i = tid * 2 + j;            // 0..511
            int k = i >> 5, seg = i & 31;   // 32 x 16B per 512B k-row
            cp_async16(smem_u32(&Bs[buf][k][seg * 4]),
                       &W[(size_t)(k0 + k) * NCOL + colTile + seg * 4]);
        }
    };

    // prologue
    loadA(0, 0); loadB(0, 0); cp_commit();
    cp_wait0();
    __syncthreads();

    int cur = 0;
    for (int chunk = 0; chunk < 16; chunk++){
        if (chunk < 15){
            loadA((chunk + 1) * 16, cur ^ 1);
            loadB((chunk + 1) * 16, cur ^ 1);
            cp_commit();
        }

        #pragma unroll
        for (int kb = 0; kb < 2; kb++){
            unsigned a[2][4];
            #pragma unroll
            for (int f = 0; f < 2; f++){
                int r0 = wm * 32 + f * 16 + gid;
                a[f][0] = tf32_(As[cur][r0][kb * 8 + tig]);
                a[f][1] = tf32_(As[cur][r0 + 8][kb * 8 + tig]);
                a[f][2] = tf32_(As[cur][r0][kb * 8 + tig + 4]);
                a[f][3] = tf32_(As[cur][r0 + 8][kb * 8 + tig + 4]);
            }
            #pragma unroll
            for (int j = 0; j < 8; j++){
                int c = wn * 64 + j * 8 + gid;
                unsigned b0 = tf32_(Bs[cur][kb * 8 + tig][c]);
                unsigned b1 = tf32_(Bs[cur][kb * 8 + tig + 4][c]);
                mma1688(d[0][j], a[0], b0, b1);
                mma1688(d[1][j], a[1], b0, b1);
            }
        }

        if (chunk < 15){
            cp_wait0();
            __syncthreads();
            cur ^= 1;
        }
    }

    // epilogue: bias + write float2 pairs into permuted zx layout
    #pragma unroll
    for (int j = 0; j < 8; j++){
        int c = colTile + wn * 64 + j * 8 + tig * 2;
        float bv0 = bias[c], bv1 = bias[c + 1];
        int jp = jperm(c);
        #pragma unroll
        for (int f = 0; f < 2; f++){
            int r0 = rowTile + wm * 32 + f * 16 + gid;
            float2 lo = { d[f][j][0] + bv0, d[f][j][1] + bv1 };
            float2 hi = { d[f][j][2] + bv0, d[f][j][3] + bv1 };
            *(float2*)&g_zx[(size_t)r0 * NCOL + jp]       = lo;
            *(float2*)&g_zx[(size_t)(r0 + 8) * NCOL + jp] = hi;
        }
    }
}

// ----------------------------- phase 2: the recurrence (unchanged from R12) -----------------------------
__global__ void __cluster_dims__(8, 1, 1) __launch_bounds__(512, 1)
lstm_chain_kernel(const float* __restrict__ W, const float* __restrict__ h0,
                  const float* __restrict__ c0, float* __restrict__ out)
{
    __shared__ __align__(16) float h_buf[2][2][HROW];   // [parity][chain][padded k]
    __shared__ __align__(16) float zx_s[4][2][128];     // [slot][chain][g*32+m]
    __shared__ __align__(8) unsigned long long mbar[2];

    const int tid  = threadIdx.x;
    const int p    = blockIdx.x >> 3;
    const int r    = blockIdx.x & 7;
    const int lane = tid & 31;

    const int m  = tid >> 4;     // 0..31 unit (local)
    const int ks = tid & 15;     // k-slice

    unsigned long long w2[32];
    {
        const float* Wb = W + (size_t)(256 + ks * 16) * NCOL + r * 32 + m;
        #pragma unroll
        for (int g = 0; g < 4; g++)
            #pragma unroll
            for (int q = 0; q < 8; q++)
                w2[g * 8 + q] = pack2(Wb[(size_t)(2 * q) * NCOL + g * 256],
                                      Wb[(size_t)(2 * q + 1) * NCOL + g * 256]);
    }

    const unsigned hb_base = smem_u32(&h_buf[0][0][0]);
    const unsigned mb_base = smem_u32(&mbar[0]);
    const int dMB = (int)(mb_base - hb_base);

    const float* zx_src = g_zx + (size_t)(2 * p) * NCOL + r * 128;
    const size_t zx_step = (size_t)BATCH * NCOL;

    if (tid == 511) {
        mbar_init(mb_base, 1);
        mbar_init(mb_base + 8, 1);
        mbar_arm(mb_base, 3072);      // waited at s=2: h(s=1) + zx(s=2)
        mbar_arm(mb_base + 8, 3072);  // waited at s=1: h(s=0) + zx(s=1)
        bulk_g2s(smem_u32(&zx_s[1][0][0]), zx_src + 1 * zx_step,        512, mb_base + 8);
        bulk_g2s(smem_u32(&zx_s[1][1][0]), zx_src + 1 * zx_step + NCOL, 512, mb_base + 8);
    }

    {
        int ch = tid >> 8, k = tid & 255;
        h_buf[0][ch][k + ((k >> 4) << 2)] = h0[(size_t)(2 * p + ch) * HID + k];
    }

    const int v_ch   = (ks >> 2) & 1;
    const int v_gate = ks & 3;
    const bool owner = (v_gate == 1) && (ks < 8);

    float cst = 0.0f;
    if (v_gate == 1) cst = c0[(size_t)(2 * p + v_ch) * HID + r * 32 + m];

    float zx0v = __ldg(zx_src + (size_t)v_ch * NCOL + v_gate * 32 + m);

    unsigned hmap[8];
    #pragma unroll
    for (int rk = 0; rk < 8; rk++) hmap[rk] = mapa_rank(hb_base, rk);

    const int m0  = 2 * (tid >> 5);
    const int kg0 = r * 32 + m0;
    const int po0 = kg0 + ((kg0 >> 4) << 2);

    float* out_ptr = out + ((size_t)(2 * p + v_ch) * S_LEN) * HID + r * 32 + m;

    const bool sender = (lane < 8) || (lane >= 16 && lane < 24);
    const int  s_ch   = (lane < 8) ? 0 : 1;
    const int  s_rk   = lane & 7;
    const int  srcA   = s_ch ? 5 : 1;
    const int  srcB   = srcA + 16;

    const bool b0 = (ks & 1), b1 = (ks >> 1) & 1, b2 = (ks >> 2) & 1;

    __syncthreads();
    cluster_sync_();

    int ph0 = 0, ph1 = 0;

    for (int s = 0; s < S_LEN; s++) {
        const int par = s & 1;

        if (s > 0) {
            unsigned bar = mb_base + (unsigned)par * 8;
            int ph = par ? ph1 : ph0;
            if (tid < 32) mbar_wait(bar, (unsigned)ph);
            if (par) ph1 ^= 1; else ph0 ^= 1;
            __syncthreads();
            if (tid == 511) {
                mbar_arm(bar, 3072);
                if (s + 2 < S_LEN) {
                    const int slot = (s + 2) & 3;
                    const float* src = zx_src + (size_t)(s + 2) * zx_step;
                    bulk_g2s(smem_u32(&zx_s[slot][0][0]), src,        512, bar);
                    bulk_g2s(smem_u32(&zx_s[slot][1][0]), src + NCOL, 512, bar);
                }
            }
        } else {
            if (tid == 511) {
                bulk_g2s(smem_u32(&zx_s[2][0][0]), zx_src + 2 * zx_step,        512, mb_base);
                bulk_g2s(smem_u32(&zx_s[2][1][0]), zx_src + 2 * zx_step + NCOL, 512, mb_base);
            }
        }

        unsigned long long accA[4] = {0,0,0,0}, accB[4] = {0,0,0,0};
        {
            const ulonglong2* hb = (const ulonglong2*)&h_buf[par][0][ks * 20];
            ulonglong2 q0 = hb[0], q1 = hb[1], q2 = hb[2], q3 = hb[3];
            unsigned long long h8[8] = {q0.x, q0.y, q1.x, q1.y, q2.x, q2.y, q3.x, q3.y};
            #pragma unroll
            for (int g = 0; g < 4; g++)
                #pragma unroll
                for (int q = 0; q < 8; q++) fma2(accA[g], w2[g * 8 + q], h8[q]);
        }
        {
            const ulonglong2* hb = (const ulonglong2*)&h_buf[par][1][ks * 20];
            ulonglong2 q0 = hb[0], q1 = hb[1], q2 = hb[2], q3 = hb[3];
            unsigned long long h8[8] = {q0.x, q0.y, q1.x, q1.y, q2.x, q2.y, q3.x, q3.y};
            #pragma unroll
            for (int g = 0; g < 4; g++)
                #pragma unroll
                for (int q = 0; q < 8; q++) fma2(accB[g], w2[g * 8 + q], h8[q]);
        }

        float sv[8];
        #pragma unroll
        for (int g = 0; g < 4; g++) {
            sv[g]     = lo32(accA[g]) + hi32(accA[g]);
            sv[4 + g] = lo32(accB[g]) + hi32(accB[g]);
        }

        float k0v[4], k1v[2], k2v;
        #pragma unroll
        for (int j = 0; j < 4; j++) {
            float snd = b0 ? sv[2 * j] : sv[2 * j + 1];
            float rcv = __shfl_xor_sync(0xffffffffu, snd, 1);
            k0v[j] = (b0 ? sv[2 * j + 1] : sv[2 * j]) + rcv;
        }
        #pragma unroll
        for (int j = 0; j < 2; j++) {
            float snd = b1 ? k0v[2 * j] : k0v[2 * j + 1];
            float rcv = __shfl_xor_sync(0xffffffffu, snd, 2);
            k1v[j] = (b1 ? k0v[2 * j + 1] : k0v[2 * j]) + rcv;
        }
        {
            float snd = b2 ? k1v[0] : k1v[1];
            float rcv = __shfl_xor_sync(0xffffffffu, snd, 4);
            k2v = (b2 ? k1v[1] : k1v[0]) + rcv;
        }
        float F = k2v + __shfl_xor_sync(0xffffffffu, k2v, 8);

        float zx = (s == 0) ? zx0v : zx_s[s & 3][v_ch][v_gate * 32 + m];
        float t = tanha(F + zx);
        float u = (v_gate == 2) ? t : 0.5f * t;
        float w = tanha(u);
        float a = (v_gate == 2) ? w : fmaf(0.5f, w, 0.5f);

        float ax = __shfl_xor_sync(0xffffffffu, a, 2);
        float P  = a * ax;
        float Pr = __shfl_xor_sync(0xffffffffu, P, 1);

        float hn = 0.0f;
        if (v_gate == 1) {
            cst = a * cst + Pr;
            hn  = tanha(cst) * ax;
        }

        float hA = __shfl_sync(0xffffffffu, hn, srcA);
        float hB = __shfl_sync(0xffffffffu, hn, srcB);

        if (sender && (s + 1 < S_LEN)) {
            const int parN = par ^ 1;
            unsigned long long pv = pack2(hA, hB);
            unsigned off = (unsigned)(((parN * 2 + s_ch) * HROW + po0) * 4);
            unsigned mbo = (unsigned)(dMB + parN * 8);
            st_async_b64(hmap[s_rk] + off, hmap[s_rk] + mbo, pv);
        }

        if (owner)
            out_ptr[0] = hn;
        out_ptr += HID;
    }

    cluster_sync_();
}

// ----------------------------- launcher -----------------------------
extern "C" void kernel_launch(void* const* d_in, const int* in_sizes, int n_in,
                              void* d_out, int out_size) {
    const float* x    = (const float*)d_in[0];   // (32, 2048, 256)
    const float* h0   = (const float*)d_in[1];   // (1, 32, 256)
    const float* c0   = (const float*)d_in[2];   // (1, 32, 256)
    const float* W    = (const float*)d_in[3];   // (512, 1024)
    const float* bias = (const float*)d_in[4];   // (1024,)
    float* out = (float*)d_out;

    const long long main_elems = (long long)BATCH * S_LEN * HID;
    const long long tail = (long long)out_size - main_elems;

    gemm_x_kernel<<<dim3(8, 512, 1), 256>>>(x, W, bias, out, main_elems, tail > 0 ? tail : 0);
    lstm_chain_kernel<<<128, 512>>>(W, h0, c0, out);
}

// round 14
// speedup vs baseline: 1.7067x; 1.0079x over previous
#include <cuda_runtime.h>
#include <cstdint>

#define S_LEN 2048
#define BATCH 32
#define HID   256
#define NCOL  1024   // 4*H
#define HROW  320    // 256 + 4-float pad per 16 floats (conflict-free LDS phases)

// 256 MB scratch for Zx = x @ Wx + b.
// Layout: [s][b][jp], jp = r*128 + g*32 + m  -> per-CTA per-chain step slice is
// one contiguous 512B block (cp.async.bulk friendly).
__device__ float g_zx[(size_t)S_LEN * BATCH * NCOL];

// ----------------------------- helpers -----------------------------
__device__ __forceinline__ void fma2(unsigned long long &d, unsigned long long a, unsigned long long b) {
    asm("fma.rn.f32x2 %0, %1, %2, %0;" : "+l"(d) : "l"(a), "l"(b));
}
__device__ __forceinline__ unsigned long long pack2(float lo, float hi) {
    unsigned long long r; asm("mov.b64 %0, {%1, %2};" : "=l"(r) : "f"(lo), "f"(hi)); return r;
}
__device__ __forceinline__ float lo32(unsigned long long v){ return __uint_as_float((unsigned)(v & 0xffffffffull)); }
__device__ __forceinline__ float hi32(unsigned long long v){ return __uint_as_float((unsigned)(v >> 32)); }
__device__ __forceinline__ unsigned smem_u32(const void* p){ return (unsigned)__cvta_generic_to_shared(p); }
__device__ __forceinline__ unsigned mapa_rank(unsigned a, unsigned rk){
    unsigned r; asm("mapa.shared::cluster.u32 %0, %1, %2;" : "=r"(r) : "r"(a), "r"(rk)); return r;
}
__device__ __forceinline__ void cluster_sync_(){
    asm volatile("barrier.cluster.arrive.aligned;" ::: "memory");
    asm volatile("barrier.cluster.wait.aligned;" ::: "memory");
}
__device__ __forceinline__ float tanha(float x){
    float y; asm("tanh.approx.f32 %0, %1;" : "=f"(y) : "f"(x)); return y;
}
__device__ __forceinline__ float sig(float x){ return fmaf(0.5f, tanha(0.5f * x), 0.5f); }

__device__ __forceinline__ void mbar_init(unsigned bar, unsigned cnt){
    asm volatile("mbarrier.init.shared.b64 [%0], %1;" :: "r"(bar), "r"(cnt) : "memory");
}
__device__ __forceinline__ void mbar_arm(unsigned bar, unsigned tx){
    asm volatile("mbarrier.arrive.expect_tx.shared.b64 _, [%0], %1;" :: "r"(bar), "r"(tx) : "memory");
}
__device__ __forceinline__ void mbar_wait(unsigned bar, unsigned parity){
    asm volatile(
        "{\n\t.reg .pred P;\n\t"
        "WL_%=:\n\t"
        "mbarrier.try_wait.parity.acquire.cluster.shared::cta.b64 P, [%0], %1, 0x989680;\n\t"
        "@!P bra WL_%=;\n\t}"
        :: "r"(bar), "r"(parity) : "memory");
}
__device__ __forceinline__ void st_async_b64(unsigned raddr, unsigned rbar, unsigned long long v){
    asm volatile("st.async.shared::cluster.mbarrier::complete_tx::bytes.b64 [%0], %1, [%2];"
                 :: "r"(raddr), "l"(v), "r"(rbar) : "memory");
}
__device__ __forceinline__ void bulk_g2s(unsigned dst, const void* src, unsigned bytes, unsigned bar){
    asm volatile("cp.async.bulk.shared::cluster.global.mbarrier::complete_tx::bytes [%0], [%1], %2, [%3];"
                 :: "r"(dst), "l"(src), "r"(bytes), "r"(bar) : "memory");
}
__device__ __forceinline__ void cp_async16(unsigned dst, const void* src){
    asm volatile("cp.async.cg.shared.global [%0], [%1], 16;" :: "r"(dst), "l"(src));
}
__device__ __forceinline__ void cp_commit(){ asm volatile("cp.async.commit_group;" ::: "memory"); }
__device__ __forceinline__ void cp_wait0(){ asm volatile("cp.async.wait_group 0;" ::: "memory"); }

__device__ __forceinline__ int jperm(int col){
    return ((col >> 5) & 7) * 128 + (col >> 8) * 32 + (col & 31);
}

__device__ __forceinline__ unsigned tf32_(float f){
    unsigned r; asm("cvt.rna.tf32.f32 %0, %1;" : "=r"(r) : "f"(f)); return r;
}
__device__ __forceinline__ void mma1688(float* d, const unsigned* a, unsigned b0, unsigned b1){
    asm("mma.sync.aligned.m16n8k8.row.col.f32.tf32.tf32.f32 "
        "{%0,%1,%2,%3}, {%4,%5,%6,%7}, {%8,%9}, {%0,%1,%2,%3};"
        : "+f"(d[0]), "+f"(d[1]), "+f"(d[2]), "+f"(d[3])
        : "r"(a[0]), "r"(a[1]), "r"(a[2]), "r"(a[3]), "r"(b0), "r"(b1));
}

// ----------------------------- phase 1: Zx = x @ Wx + b (tf32 tensor cores) -----------------------------
// 128x128 tile, 8 warps (warp-tile 32x64), K=16 double-buffered chunks fed by
// cp.async for BOTH operands. Bank-engineered strides: As[128][20], Bs[16][136].
__global__ void __launch_bounds__(256)
gemm_x_kernel(const float* __restrict__ x, const float* __restrict__ W, const float* __restrict__ bias,
              float* __restrict__ out, long long tail_start, long long tail_n)
{
    __shared__ float As[2][128][20];   // [buf][row][k]
    __shared__ float Bs[2][16][136];   // [buf][k][col]

    const int tid = threadIdx.x;

    if (blockIdx.x == 0 && blockIdx.y < 64) {
        long long i = (long long)blockIdx.y * 256 + tid;
        if (i < tail_n) out[tail_start + i] = 0.0f;
    }

    const int colTile = blockIdx.x * 128;
    const int rowTile = blockIdx.y * 128;

    const int wid = tid >> 5, lane = tid & 31;
    const int wm = wid & 3;
    const int wn = wid >> 2;
    const int gid = lane >> 2;
    const int tig = lane & 3;

    float d[2][8][4];
    #pragma unroll
    for (int f = 0; f < 2; f++)
        #pragma unroll
        for (int j = 0; j < 8; j++)
            #pragma unroll
            for (int q = 0; q < 4; q++) d[f][j][q] = 0.0f;

    auto loadA = [&](int k0, int buf){
        #pragma unroll
        for (int j = 0; j < 2; j++){
            int i = tid * 2 + j;
            int row = i >> 2, seg = i & 3;
            int rr = rowTile + row;
            int bb = rr & 31, ss = rr >> 5;
            cp_async16(smem_u32(&As[buf][row][seg * 4]),
                       &x[((size_t)bb * S_LEN + ss) * 256 + k0 + seg * 4]);
        }
    };
    auto loadB = [&](int k0, int buf){
        #pragma unroll
        for (int j = 0; j < 2; j++){
            int i = tid * 2 + j;
            int k = i >> 5, seg = i & 31;
            cp_async16(smem_u32(&Bs[buf][k][seg * 4]),
                       &W[(size_t)(k0 + k) * NCOL + colTile + seg * 4]);
        }
    };

    loadA(0, 0); loadB(0, 0); cp_commit();
    cp_wait0();
    __syncthreads();

    int cur = 0;
    for (int chunk = 0; chunk < 16; chunk++){
        if (chunk < 15){
            loadA((chunk + 1) * 16, cur ^ 1);
            loadB((chunk + 1) * 16, cur ^ 1);
            cp_commit();
        }

        #pragma unroll
        for (int kb = 0; kb < 2; kb++){
            unsigned a[2][4];
            #pragma unroll
            for (int f = 0; f < 2; f++){
                int r0 = wm * 32 + f * 16 + gid;
                a[f][0] = tf32_(As[cur][r0][kb * 8 + tig]);
                a[f][1] = tf32_(As[cur][r0 + 8][kb * 8 + tig]);
                a[f][2] = tf32_(As[cur][r0][kb * 8 + tig + 4]);
                a[f][3] = tf32_(As[cur][r0 + 8][kb * 8 + tig + 4]);
            }
            #pragma unroll
            for (int j = 0; j < 8; j++){
                int c = wn * 64 + j * 8 + gid;
                unsigned b0 = tf32_(Bs[cur][kb * 8 + tig][c]);
                unsigned b1 = tf32_(Bs[cur][kb * 8 + tig + 4][c]);
                mma1688(d[0][j], a[0], b0, b1);
                mma1688(d[1][j], a[1], b0, b1);
            }
        }

        if (chunk < 15){
            cp_wait0();
            __syncthreads();
            cur ^= 1;
        }
    }

    #pragma unroll
    for (int j = 0; j < 8; j++){
        int c = colTile + wn * 64 + j * 8 + tig * 2;
        float bv0 = bias[c], bv1 = bias[c + 1];
        int jp = jperm(c);
        #pragma unroll
        for (int f = 0; f < 2; f++){
            int r0 = rowTile + wm * 32 + f * 16 + gid;
            float2 lo = { d[f][j][0] + bv0, d[f][j][1] + bv1 };
            float2 hi = { d[f][j][2] + bv0, d[f][j][3] + bv1 };
            *(float2*)&g_zx[(size_t)r0 * NCOL + jp]       = lo;
            *(float2*)&g_zx[(size_t)(r0 + 8) * NCOL + jp] = hi;
        }
    }
}

// ----------------------------- phase 2: the recurrence -----------------------------
// Same dataflow as R13; sync path shortened: ALL warps sleep on the mbarrier
// (acquire per warp) and the post-wait __syncthreads is removed. Re-arm by
// warp 15 precedes its own sends (program order) -> no arrival race; zx slot
// reuse stays transitively ordered through the h-dependence chain.
__global__ void __cluster_dims__(8, 1, 1) __launch_bounds__(512, 1)
lstm_chain_kernel(const float* __restrict__ W, const float* __restrict__ h0,
                  const float* __restrict__ c0, float* __restrict__ out)
{
    __shared__ __align__(16) float h_buf[2][2][HROW];   // [parity][chain][padded k]
    __shared__ __align__(16) float zx_s[4][2][128];     // [slot][chain][g*32+m]
    __shared__ __align__(8) unsigned long long mbar[2];

    const int tid  = threadIdx.x;
    const int p    = blockIdx.x >> 3;
    const int r    = blockIdx.x & 7;
    const int lane = tid & 31;

    const int m  = tid >> 4;     // 0..31 unit (local)
    const int ks = tid & 15;     // k-slice

    unsigned long long w2[32];
    {
        const float* Wb = W + (size_t)(256 + ks * 16) * NCOL + r * 32 + m;
        #pragma unroll
        for (int g = 0; g < 4; g++)
            #pragma unroll
            for (int q = 0; q < 8; q++)
                w2[g * 8 + q] = pack2(Wb[(size_t)(2 * q) * NCOL + g * 256],
                                      Wb[(size_t)(2 * q + 1) * NCOL + g * 256]);
    }

    const unsigned hb_base = smem_u32(&h_buf[0][0][0]);
    const unsigned mb_base = smem_u32(&mbar[0]);
    const int dMB = (int)(mb_base - hb_base);

    const float* zx_src = g_zx + (size_t)(2 * p) * NCOL + r * 128;
    const size_t zx_step = (size_t)BATCH * NCOL;

    if (tid == 511) {
        mbar_init(mb_base, 1);
        mbar_init(mb_base + 8, 1);
        mbar_arm(mb_base, 3072);      // waited at s=2: h(s=1) + zx(s=2)
        mbar_arm(mb_base + 8, 3072);  // waited at s=1: h(s=0) + zx(s=1)
        bulk_g2s(smem_u32(&zx_s[1][0][0]), zx_src + 1 * zx_step,        512, mb_base + 8);
        bulk_g2s(smem_u32(&zx_s[1][1][0]), zx_src + 1 * zx_step + NCOL, 512, mb_base + 8);
    }

    {
        int ch = tid >> 8, k = tid & 255;
        h_buf[0][ch][k + ((k >> 4) << 2)] = h0[(size_t)(2 * p + ch) * HID + k];
    }

    const int v_ch   = (ks >> 2) & 1;
    const int v_gate = ks & 3;
    const bool owner = (v_gate == 1) && (ks < 8);

    float cst = 0.0f;
    if (v_gate == 1) cst = c0[(size_t)(2 * p + v_ch) * HID + r * 32 + m];

    float zx0v = __ldg(zx_src + (size_t)v_ch * NCOL + v_gate * 32 + m);

    unsigned hmap[8];
    #pragma unroll
    for (int rk = 0; rk < 8; rk++) hmap[rk] = mapa_rank(hb_base, rk);

    const int m0  = 2 * (tid >> 5);
    const int kg0 = r * 32 + m0;
    const int po0 = kg0 + ((kg0 >> 4) << 2);

    float* out_ptr = out + ((size_t)(2 * p + v_ch) * S_LEN) * HID + r * 32 + m;

    const bool sender = (lane < 8) || (lane >= 16 && lane < 24);
    const int  s_ch   = (lane < 8) ? 0 : 1;
    const int  s_rk   = lane & 7;
    const int  srcA   = s_ch ? 5 : 1;
    const int  srcB   = srcA + 16;

    const bool b0 = (ks & 1), b1 = (ks >> 1) & 1, b2 = (ks >> 2) & 1;

    __syncthreads();
    cluster_sync_();

    int ph0 = 0, ph1 = 0;

    for (int s = 0; s < S_LEN; s++) {
        const int par = s & 1;

        if (s > 0) {
            unsigned bar = mb_base + (unsigned)par * 8;
            int ph = par ? ph1 : ph0;
            mbar_wait(bar, (unsigned)ph);      // ALL warps sleep; per-warp acquire
            if (par) ph1 ^= 1; else ph0 ^= 1;
            if (tid == 511) {
                mbar_arm(bar, 3072);           // phase used at s+2
                if (s + 2 < S_LEN) {
                    const int slot = (s + 2) & 3;
                    const float* src = zx_src + (size_t)(s + 2) * zx_step;
                    bulk_g2s(smem_u32(&zx_s[slot][0][0]), src,        512, bar);
                    bulk_g2s(smem_u32(&zx_s[slot][1][0]), src + NCOL, 512, bar);
                }
            }
        } else {
            if (tid == 511) {
                bulk_g2s(smem_u32(&zx_s[2][0][0]), zx_src + 2 * zx_step,        512, mb_base);
                bulk_g2s(smem_u32(&zx_s[2][1][0]), zx_src + 2 * zx_step + NCOL, 512, mb_base);
            }
        }

        unsigned long long accA[4] = {0,0,0,0}, accB[4] = {0,0,0,0};
        {
            const ulonglong2* hb = (const ulonglong2*)&h_buf[par][0][ks * 20];
            ulonglong2 q0 = hb[0], q1 = hb[1], q2 = hb[2], q3 = hb[3];
            unsigned long long h8[8] = {q0.x, q0.y, q1.x, q1.y, q2.x, q2.y, q3.x, q3.y};
            #pragma unroll
            for (int g = 0; g < 4; g++)
                #pragma unroll
                for (int q = 0; q < 8; q++) fma2(accA[g], w2[g * 8 + q], h8[q]);
        }
        {
            const ulonglong2* hb = (const ulonglong2*)&h_buf[par][1][ks * 20];
            ulonglong2 q0 = hb[0], q1 = hb[1], q2 = hb[2], q3 = hb[3];
            unsigned long long h8[8] = {q0.x, q0.y, q1.x, q1.y, q2.x, q2.y, q3.x, q3.y};
            #pragma unroll
            for (int g = 0; g < 4; g++)
                #pragma unroll
                for (int q = 0; q < 8; q++) fma2(accB[g], w2[g * 8 + q], h8[q]);
        }

        float sv[8];
        #pragma unroll
        for (int g = 0; g < 4; g++) {
            sv[g]     = lo32(accA[g]) + hi32(accA[g]);
            sv[4 + g] = lo32(accB[g]) + hi32(accB[g]);
        }

        float k0v[4], k1v[2], k2v;
        #pragma unroll
        for (int j = 0; j < 4; j++) {
            float snd = b0 ? sv[2 * j] : sv[2 * j + 1];
            float rcv = __shfl_xor_sync(0xffffffffu, snd, 1);
            k0v[j] = (b0 ? sv[2 * j + 1] : sv[2 * j]) + rcv;
        }
        #pragma unroll
        for (int j = 0; j < 2; j++) {
            float snd = b1 ? k0v[2 * j] : k0v[2 * j + 1];
            float rcv = __shfl_xor_sync(0xffffffffu, snd, 2);
            k1v[j] = (b1 ? k0v[2 * j + 1] : k0v[2 * j]) + rcv;
        }
        {
            float snd = b2 ? k1v[0] : k1v[1];
            float rcv = __shfl_xor_sync(0xffffffffu, snd, 4);
            k2v = (b2 ? k1v[1] : k1v[0]) + rcv;
        }
        float F = k2v + __shfl_xor_sync(0xffffffffu, k2v, 8);

        float zx = (s == 0) ? zx0v : zx_s[s & 3][v_ch][v_gate * 32 + m];
        float t = tanha(F + zx);
        float u = (v_gate == 2) ? t : 0.5f * t;
        float w = tanha(u);
        float a = (v_gate == 2) ? w : fmaf(0.5f, w, 0.5f);

        float ax = __shfl_xor_sync(0xffffffffu, a, 2);
        float P  = a * ax;
        float Pr = __shfl_xor_sync(0xffffffffu, P, 1);

        float hn = 0.0f;
        if (v_gate == 1) {
            cst = a * cst + Pr;
            hn  = tanha(cst) * ax;
        }

        float hA = __shfl_sync(0xffffffffu, hn, srcA);
        float hB = __shfl_sync(0xffffffffu, hn, srcB);

        if (sender && (s + 1 < S_LEN)) {
            const int parN = par ^ 1;
            unsigned long long pv = pack2(hA, hB);
            unsigned off = (unsigned)(((parN * 2 + s_ch) * HROW + po0) * 4);
            unsigned mbo = (unsigned)(dMB + parN * 8);
            st_async_b64(hmap[s_rk] + off, hmap[s_rk] + mbo, pv);
        }

        if (owner)
            out_ptr[0] = hn;
        out_ptr += HID;
    }

    cluster_sync_();
}

// ----------------------------- launcher -----------------------------
extern "C" void kernel_launch(void* const* d_in, const int* in_sizes, int n_in,
                              void* d_out, int out_size) {
    const float* x    = (const float*)d_in[0];   // (32, 2048, 256)
    const float* h0   = (const float*)d_in[1];   // (1, 32, 256)
    const float* c0   = (const float*)d_in[2];   // (1, 32, 256)
    const float* W    = (const float*)d_in[3];   // (512, 1024)
    const float* bias = (const float*)d_in[4];   // (1024,)
    float* out = (float*)d_out;

    const long long main_elems = (long long)BATCH * S_LEN * HID;
    const long long tail = (long long)out_size - main_elems;

    gemm_x_kernel<<<dim3(8, 512, 1), 256>>>(x, W, bias, out, main_elems, tail > 0 ? tail : 0);
    lstm_chain_kernel<<<128, 512>>>(W, h0, c0, out);
}